// round 6
// baseline (speedup 1.0000x reference)
#include <cuda_runtime.h>
#include <cuda_bf16.h>
#include <math.h>
#include <stdint.h>

#define DIMM 768
#define DIN_ 1024
#define NQ_ 384
#define NB_ 12
#define BATCH_ 2
#define LSEQ_ 1024
#define DI_ 1536
#define DS_ 16
#define DC_ 4
#define DTR_ 48
#define NH_ 16
#define HD_ 48
#define NM_ 14

// ---------------- arena (sizes in floats) ----------------
#define SZ_BL_DIM   (BATCH_*LSEQ_*DIMM)
#define SZ_XZ       (BATCH_*LSEQ_*2*DI_)
#define SZ_XC       (BATCH_*LSEQ_*DI_)
#define SZ_DBL      (BATCH_*LSEQ_*80)
#define SZ_Q_DIM    (BATCH_*NQ_*DIMM)
#define SZ_CAT      (BATCH_*NQ_*2*DIMM)
#define SZ_KVW      (NB_*2*DIMM*DIMM)
#define SZ_KVB      (NB_*2*DIMM)
#define SZ_KVALL    (BATCH_*LSEQ_*NB_*2*DIMM)
#define SZ_PART     (8*1024*1024)

#define OFF_FEATS  ((size_t)0)
#define OFF_FWD    (OFF_FEATS + SZ_BL_DIM)
#define OFF_FLIP   (OFF_FWD   + SZ_BL_DIM)
#define OFF_C      (OFF_FLIP  + SZ_BL_DIM)
#define OFF_MO     (OFF_C     + SZ_BL_DIM)
#define OFF_XZ     (OFF_MO    + SZ_BL_DIM)
#define OFF_XCB    (OFF_XZ    + SZ_XZ)
#define OFF_DBL    (OFF_XCB   + SZ_XC)
#define OFF_DT     (OFF_DBL   + SZ_DBL)
#define OFF_YS     (OFF_DT    + SZ_XC)
#define OFF_X      (OFF_YS    + SZ_XC)
#define OFF_XN     (OFF_X     + SZ_Q_DIM)
#define OFF_QB     (OFF_XN    + SZ_Q_DIM)
#define OFF_OB     (OFF_QB    + SZ_Q_DIM)
#define OFF_CAT    (OFF_OB    + SZ_Q_DIM)
#define OFF_KVW    (OFF_CAT   + SZ_CAT)
#define OFF_KVB    (OFF_KVW   + SZ_KVW)
#define OFF_KVALL  (OFF_KVB   + SZ_KVB)
#define OFF_PART   (OFF_KVALL + SZ_KVALL)
#define ARENA_SZ   (OFF_PART  + SZ_PART)

__device__ __align__(256) float g_arena[ARENA_SZ];

// ---------------- helpers ----------------
__device__ __forceinline__ float softplusf(float x) {
    return fmaxf(x, 0.f) + log1pf(expf(-fabsf(x)));
}
__device__ __forceinline__ float siluf(float x) {
    return x / (1.f + expf(-x));
}
__device__ __forceinline__ void cvt2(float x, float y, uint32_t& hi, uint32_t& lo) {
    __nv_bfloat162 h2 = __floats2bfloat162_rn(x, y);
    float hx = __bfloat162float(__low2bfloat16(h2));
    float hy = __bfloat162float(__high2bfloat16(h2));
    __nv_bfloat162 l2 = __floats2bfloat162_rn(x - hx, y - hy);
    hi = *reinterpret_cast<uint32_t*>(&h2);
    lo = *reinterpret_cast<uint32_t*>(&l2);
}

#define MMA_BF16(d, a, b0, b1) \
    asm volatile("mma.sync.aligned.m16n8k16.row.col.f32.bf16.bf16.f32 " \
        "{%0,%1,%2,%3}, {%4,%5,%6,%7}, {%8,%9}, {%0,%1,%2,%3};" \
        : "+f"(d[0]), "+f"(d[1]), "+f"(d[2]), "+f"(d[3]) \
        : "r"(a[0]), "r"(a[1]), "r"(a[2]), "r"(a[3]), "r"(b0), "r"(b1))

#define LDSM4(r, addr) \
    asm volatile("ldmatrix.sync.aligned.m8n8.x4.shared.b16 {%0,%1,%2,%3}, [%4];" \
        : "=r"((r)[0]), "=r"((r)[1]), "=r"((r)[2]), "=r"((r)[3]) : "r"(addr))

// ================= bf16x2 tensor-core GEMM (ldmatrix mainloop) =================
// 128x128 tile, BK=32, 256 thr, warps 4(M)x2(N), warp tile 32x64.
// smem per stage: ah|al|bh|bl tiles, each 128 rows x PSTR uint32 (bf16x2 pairs).
#define PSTR 20
#define STG (128 * PSTR)
#define STG4 (STG * 4)
#define BF16_SMEM (2 * 4 * STG * 4)

__global__ __launch_bounds__(256, 2) void gemm_bf16x2_kernel(
    const float* __restrict__ A, int lda,
    const float* __restrict__ B, int ldb,
    const float* __restrict__ bias,
    const float* __restrict__ addend, int ldadd,
    float* __restrict__ C, int ldc, size_t zstride,
    int M, int N, int klen, int act)
{
    extern __shared__ uint32_t sm_[];
    int tid = threadIdx.x;
    int bm = blockIdx.y * 128, bn = blockIdx.x * 128;
    int kbeg = blockIdx.z * klen, kend = kbeg + klen;

    int lrow = tid & 127;
    int khalf = tid >> 7;
    int arow = bm + lrow, brow = bn + lrow;
    bool avalid = arow < M, bvalid = brow < N;
    const float* Ap = A + (size_t)(avalid ? arow : 0) * lda;
    const float* Bp = B + (size_t)(bvalid ? brow : 0) * ldb;

    float4 stA[4], stB[4];

    auto gload = [&](int kbase) {
        int k0 = kbase + khalf * 16;
        const float4 z4 = make_float4(0.f, 0.f, 0.f, 0.f);
#pragma unroll
        for (int q = 0; q < 4; q++) {
            int k = k0 + q * 4;
            bool kin = k < kend;
            stA[q] = (avalid && kin) ? *(const float4*)(Ap + k) : z4;
            stB[q] = (bvalid && kin) ? *(const float4*)(Bp + k) : z4;
        }
    };

    auto ssave = [&](int p) {
        uint32_t* base = sm_ + (size_t)p * 4 * STG;
        uint32_t* ah = base;
        uint32_t* al = base + STG;
        uint32_t* bh = base + 2 * STG;
        uint32_t* bl = base + 3 * STG;
        int col0 = khalf * 8;
#pragma unroll
        for (int qq = 0; qq < 2; qq++) {
            uint4 h4, l4;
            cvt2(stA[2*qq].x,   stA[2*qq].y,   h4.x, l4.x);
            cvt2(stA[2*qq].z,   stA[2*qq].w,   h4.y, l4.y);
            cvt2(stA[2*qq+1].x, stA[2*qq+1].y, h4.z, l4.z);
            cvt2(stA[2*qq+1].z, stA[2*qq+1].w, h4.w, l4.w);
            *(uint4*)&ah[lrow * PSTR + col0 + qq * 4] = h4;
            *(uint4*)&al[lrow * PSTR + col0 + qq * 4] = l4;
            cvt2(stB[2*qq].x,   stB[2*qq].y,   h4.x, l4.x);
            cvt2(stB[2*qq].z,   stB[2*qq].w,   h4.y, l4.y);
            cvt2(stB[2*qq+1].x, stB[2*qq+1].y, h4.z, l4.z);
            cvt2(stB[2*qq+1].z, stB[2*qq+1].w, h4.w, l4.w);
            *(uint4*)&bh[lrow * PSTR + col0 + qq * 4] = h4;
            *(uint4*)&bl[lrow * PSTR + col0 + qq * 4] = l4;
        }
    };

    gload(kbeg);
    ssave(0);
    __syncthreads();

    int lane = tid & 31, warp = tid >> 5;
    int wm = warp & 3, wn = warp >> 2;
    int m0 = wm * 32, n0 = wn * 64;
    int lr = lane >> 2, lc = lane & 3;

    // ldmatrix per-lane base byte-offsets
    uint32_t smem_base = (uint32_t)__cvta_generic_to_shared(sm_);
    int j8 = lane >> 3, rj = lane & 7;
    int arow_l = ((j8 & 1) << 3) + rj;     // row within 16-row A tile
    int akq = (j8 >> 1) * 4;               // k-quarter (uint32) for A
    uint32_t aoff[2];
#pragma unroll
    for (int mi = 0; mi < 2; mi++)
        aoff[mi] = ((m0 + mi * 16 + arow_l) * PSTR + akq) * 4;
    int brow_l = ((j8 >> 1) << 3) + rj;    // row within 16-row B pair-tile
    int bkq = (j8 & 1) * 4;
    uint32_t boff[4];
#pragma unroll
    for (int pr = 0; pr < 4; pr++)
        boff[pr] = ((n0 + pr * 16 + brow_l) * PSTR + bkq) * 4;

    float acc[2][8][4];
#pragma unroll
    for (int mi = 0; mi < 2; mi++)
#pragma unroll
        for (int ni = 0; ni < 8; ni++)
#pragma unroll
            for (int r = 0; r < 4; r++) acc[mi][ni][r] = 0.f;

    int p = 0;
    int nsteps = (klen + 31) / 32;
    for (int step = 0; step < nsteps; step++) {
        bool more = (step + 1 < nsteps);
        if (more) gload(kbeg + (step + 1) * 32);

        uint32_t sb = smem_base + (uint32_t)p * 4 * STG4;
#pragma unroll
        for (int c = 0; c < 2; c++) {
            uint32_t kboff = c * 32;     // 8 uint32 = 32 bytes
            uint32_t afh[2][4], afl[2][4];
#pragma unroll
            for (int mi = 0; mi < 2; mi++) {
                LDSM4(afh[mi], sb + aoff[mi] + kboff);
                LDSM4(afl[mi], sb + STG4 + aoff[mi] + kboff);
            }
#pragma unroll
            for (int pr = 0; pr < 4; pr++) {
                uint32_t bhm[4], blm[4];
                LDSM4(bhm, sb + 2 * STG4 + boff[pr] + kboff);
                LDSM4(blm, sb + 3 * STG4 + boff[pr] + kboff);
#pragma unroll
                for (int mi = 0; mi < 2; mi++) {
                    MMA_BF16(acc[mi][2*pr],   afh[mi], bhm[0], bhm[1]);
                    MMA_BF16(acc[mi][2*pr],   afh[mi], blm[0], blm[1]);
                    MMA_BF16(acc[mi][2*pr],   afl[mi], bhm[0], bhm[1]);
                    MMA_BF16(acc[mi][2*pr+1], afh[mi], bhm[2], bhm[3]);
                    MMA_BF16(acc[mi][2*pr+1], afh[mi], blm[2], blm[3]);
                    MMA_BF16(acc[mi][2*pr+1], afl[mi], bhm[2], bhm[3]);
                }
            }
        }
        if (more) {
            ssave(p ^ 1);
            __syncthreads();
            p ^= 1;
        }
    }

    // ---- epilogue ----
    float* Cz = C + (size_t)blockIdx.z * zstride;
#pragma unroll
    for (int mi = 0; mi < 2; mi++) {
#pragma unroll
        for (int rh = 0; rh < 2; rh++) {
            int m = bm + m0 + mi * 16 + lr + rh * 8;
            if (m >= M) continue;
#pragma unroll
            for (int ni = 0; ni < 8; ni++) {
#pragma unroll
                for (int cc = 0; cc < 2; cc++) {
                    int n = bn + n0 + ni * 8 + 2 * lc + cc;
                    if (n >= N) continue;
                    float v = acc[mi][ni][rh * 2 + cc];
                    if (bias) v += bias[n];
                    if (act == 1) v = softplusf(v);
                    if (addend) v += addend[(size_t)m * ldadd + n];
                    Cz[(size_t)m * ldc + n] = v;
                }
            }
        }
    }
}

// ============ split-K reduce with epilogue ============
__global__ void reduce_kernel(const float* __restrict__ part, size_t pstride, int nsplit,
                              const float* __restrict__ bias,
                              const float* __restrict__ addend, int ldadd,
                              float* __restrict__ C, int ldc, int M, int N, int act)
{
    int idx = blockIdx.x * blockDim.x + threadIdx.x;
    if (idx >= M * N) return;
    int m = idx / N, n = idx % N;
    float v = 0.f;
    for (int z = 0; z < nsplit; z++) v += part[(size_t)z * pstride + idx];
    if (bias) v += bias[n];
    if (act == 1) v = softplusf(v);
    if (addend) v += addend[(size_t)m * ldadd + n];
    C[(size_t)m * ldc + n] = v;
}

static float* g_partial = nullptr;

static void gemm(const float* A, int lda, const float* B, int ldb,
                 const float* bias, const float* addend, int ldadd,
                 float* C, int ldc, int M, int N, int K, int act)
{
    int gm = (M + 127) / 128, gn = (N + 127) / 128;
    int split = 1;
    while (gm * gn * split < 132 && split < 8 &&
           (K % (split * 2)) == 0 && (K / (split * 2)) >= 48 &&
           ((K / (split * 2)) % 16) == 0) split *= 2;
    int klen = K / split;
    dim3 grid(gn, gm, split);
    if (split == 1) {
        gemm_bf16x2_kernel<<<grid, 256, BF16_SMEM>>>(
            A, lda, B, ldb, bias, addend, ldadd, C, ldc, 0, M, N, klen, act);
    } else {
        gemm_bf16x2_kernel<<<grid, 256, BF16_SMEM>>>(
            A, lda, B, ldb, nullptr, nullptr, 0,
            g_partial, N, (size_t)M * N, M, N, klen, 0);
        reduce_kernel<<<(M * N + 255) / 256, 256>>>(g_partial, (size_t)M * N, split,
                                                    bias, addend, ldadd, C, ldc, M, N, act);
    }
}

// ---------------- layernorm ----------------
__global__ void ln_kernel(const float* __restrict__ x, const float* __restrict__ g,
                          const float* __restrict__ b, float* __restrict__ y)
{
    int r = blockIdx.x;
    const float* xp = x + (size_t)r * DIMM;
    float s = 0.f, ss = 0.f;
    for (int i = threadIdx.x; i < DIMM; i += blockDim.x) {
        float v = xp[i]; s += v; ss += v * v;
    }
    __shared__ float shs[8], shss[8];
    for (int o = 16; o > 0; o >>= 1) {
        s += __shfl_xor_sync(0xffffffffu, s, o);
        ss += __shfl_xor_sync(0xffffffffu, ss, o);
    }
    int w = threadIdx.x >> 5;
    if ((threadIdx.x & 31) == 0) { shs[w] = s; shss[w] = ss; }
    __syncthreads();
    if (threadIdx.x == 0) {
        float ts = 0.f, tss = 0.f;
        int nw = blockDim.x >> 5;
        for (int i = 0; i < nw; i++) { ts += shs[i]; tss += shss[i]; }
        shs[0] = ts; shss[0] = tss;
    }
    __syncthreads();
    float mean = shs[0] / (float)DIMM;
    float var = shss[0] / (float)DIMM - mean * mean;
    float inv = rsqrtf(var + 1e-5f);
    float* yp = y + (size_t)r * DIMM;
    for (int i = threadIdx.x; i < DIMM; i += blockDim.x)
        yp[i] = (xp[i] - mean) * inv * g[i] + b[i];
}

// ---------------- depthwise causal conv + silu ----------------
__global__ void conv_kernel(const float* __restrict__ xz, const float* __restrict__ cw,
                            const float* __restrict__ cb, float* __restrict__ xc, int L)
{
    int idx = blockIdx.x * blockDim.x + threadIdx.x;
    int total = BATCH_ * L * DI_;
    if (idx >= total) return;
    int d = idx % DI_;
    int l = (idx / DI_) % L;
    int b = idx / (DI_ * L);
    float sum = cb[d];
    const float* base = xz + ((size_t)b * L) * (2 * DI_) + d;
#pragma unroll
    for (int j = 0; j < DC_; j++) {
        int lt = l - (DC_ - 1) + j;
        if (lt >= 0) sum += base[(size_t)lt * (2 * DI_)] * cw[d * DC_ + j];
    }
    xc[idx] = siluf(sum);
}

// ---------------- selective scan: 4 states/thread, 2-shfl reduce ----------------
__global__ void scan_kernel(const float* __restrict__ dt, const float* __restrict__ dbl,
                            const float* __restrict__ xc, const float* __restrict__ xz,
                            const float* __restrict__ A_log, const float* __restrict__ Dp,
                            float* __restrict__ ys, int L)
{
    int idx = blockIdx.x * blockDim.x + threadIdx.x;  // BATCH*DI*4 threads
    int sq = idx & 3;          // which state-quarter
    int s4 = sq * 4;
    int bd = idx >> 2;
    int d = bd % DI_;
    int b = bd / DI_;

    float Av[4];
#pragma unroll
    for (int q = 0; q < 4; q++) Av[q] = -__expf(A_log[d * DS_ + s4 + q]);
    float Dv = Dp[d];
    float h[4] = {0.f, 0.f, 0.f, 0.f};

    const float* dt_p = dt + (size_t)b * L * DI_ + d;
    const float* xc_p = xc + (size_t)b * L * DI_ + d;
    const float* z_p = xz + (size_t)b * L * (2 * DI_) + DI_ + d;
    const float* bl_p = dbl + (size_t)b * L * 80;
    float* ys_p = ys + (size_t)b * L * DI_ + d;

    float dtv = dt_p[0];
    float xcv = xc_p[0];
    float4 Bv = *(const float4*)(bl_p + 48 + s4);
    float4 Cv = *(const float4*)(bl_p + 64 + s4);
    float zv = (sq == 0) ? z_p[0] : 0.f;

    for (int t = 0; t < L; t++) {
        float dtn = 0.f, xcn = 0.f, zn = 0.f;
        float4 Bn = make_float4(0.f, 0.f, 0.f, 0.f);
        float4 Cn = Bn;
        if (t + 1 < L) {
            size_t t1 = t + 1;
            dtn = dt_p[t1 * DI_];
            xcn = xc_p[t1 * DI_];
            Bn = *(const float4*)(bl_p + t1 * 80 + 48 + s4);
            Cn = *(const float4*)(bl_p + t1 * 80 + 64 + s4);
            if (sq == 0) zn = z_p[t1 * (2 * DI_)];
        }
        float dx = dtv * xcv;
        float Bb[4] = {Bv.x, Bv.y, Bv.z, Bv.w};
        float Cc[4] = {Cv.x, Cv.y, Cv.z, Cv.w};
        float pr = 0.f;
#pragma unroll
        for (int q = 0; q < 4; q++) {
            h[q] = __expf(dtv * Av[q]) * h[q] + dx * Bb[q];
            pr += h[q] * Cc[q];
        }
        pr += __shfl_xor_sync(0xffffffffu, pr, 2);
        pr += __shfl_xor_sync(0xffffffffu, pr, 1);
        if (sq == 0) {
            float y = pr + Dv * xcv;
            ys_p[(size_t)t * DI_] = y * siluf(zv);
        }
        dtv = dtn; xcv = xcn; Bv = Bn; Cv = Cn; zv = zn;
    }
}

// ---------------- local cross-attention (batched kv buffer) ----------------
__global__ void attn_kernel(const float* __restrict__ q, const float* __restrict__ kv,
                            float* __restrict__ o, int ldkv, int loff)
{
    int idx = blockIdx.x * blockDim.x + threadIdx.x;
    if (idx >= BATCH_ * NQ_ * NH_) return;
    int h = idx % NH_;
    int qi = (idx / NH_) % NQ_;
    int b = idx / (NH_ * NQ_);
    const int kpq = LSEQ_ / NQ_;
    const int extra = LSEQ_ % NQ_;
    int start = qi * kpq + (qi < extra ? qi : extra);
    int cnt = kpq + (qi < extra ? 1 : 0);
    const float* qp = q + ((size_t)(b * NQ_ + qi)) * DIMM + h * HD_;
    float s[3];
    float mx = -1e30f;
    for (int j = 0; j < cnt; j++) {
        const float* kp = kv + ((size_t)(b * LSEQ_ + start + j)) * ldkv + loff + h * HD_;
        float dot = 0.f;
#pragma unroll
        for (int d = 0; d < HD_; d++) dot += qp[d] * kp[d];
        dot *= 0.14433756729740643f;
        s[j] = dot;
        if (dot > mx) mx = dot;
    }
    float sum = 0.f;
    for (int j = 0; j < cnt; j++) { s[j] = expf(s[j] - mx); sum += s[j]; }
    float inv = 1.f / sum;
    float* op = o + ((size_t)(b * NQ_ + qi)) * DIMM + h * HD_;
    for (int d = 0; d < HD_; d++) {
        float acc = 0.f;
        for (int j = 0; j < cnt; j++)
            acc += s[j] * kv[((size_t)(b * LSEQ_ + start + j)) * ldkv + loff + DIMM + h * HD_ + d];
        op[d] = acc * inv;
    }
}

// ---------------- kv weight/bias gather ----------------
__global__ void kvgather_w(const float* __restrict__ w, float* __restrict__ out)
{
    int idx = blockIdx.x * blockDim.x + threadIdx.x;
    int total = NB_ * 2 * DIMM * DIMM;
    if (idx >= total) return;
    int n = idx / DIMM, k = idx % DIMM;
    int l = n / (2 * DIMM), r = n % (2 * DIMM);
    out[idx] = w[((size_t)l * 3 * DIMM + DIMM + r) * DIMM + k];
}
__global__ void kvgather_b(const float* __restrict__ b, float* __restrict__ out)
{
    int n = blockIdx.x * blockDim.x + threadIdx.x;
    if (n >= NB_ * 2 * DIMM) return;
    int l = n / (2 * DIMM), r = n % (2 * DIMM);
    out[n] = b[(size_t)l * 3 * DIMM + DIMM + r];
}

// ---------------- elementwise utilities ----------------
__global__ void flip_kernel(const float* __restrict__ in, float* __restrict__ out, int L)
{
    int idx = blockIdx.x * blockDim.x + threadIdx.x;
    int total = BATCH_ * L * DIMM;
    if (idx >= total) return;
    int d = idx % DIMM;
    int l = (idx / DIMM) % L;
    int b = idx / (DIMM * L);
    out[idx] = in[((size_t)b * L + (L - 1 - l)) * DIMM + d];
}

__global__ void add3_kernel(const float* __restrict__ fwd, const float* __restrict__ mo,
                            const float* __restrict__ feats, float* __restrict__ c, int L)
{
    int idx = blockIdx.x * blockDim.x + threadIdx.x;
    int total = BATCH_ * L * DIMM;
    if (idx >= total) return;
    int d = idx % DIMM;
    int l = (idx / DIMM) % L;
    int b = idx / (DIMM * L);
    c[idx] = fwd[idx] + mo[((size_t)b * L + (L - 1 - l)) * DIMM + d] + feats[idx];
}

__global__ void bcast_kernel(const float* __restrict__ queries, float* __restrict__ x)
{
    int idx = blockIdx.x * blockDim.x + threadIdx.x;
    int total = BATCH_ * NQ_ * DIMM;
    if (idx >= total) return;
    x[idx] = queries[idx % (NQ_ * DIMM)];
}

__global__ void copy_kernel(const float* __restrict__ a, float* __restrict__ b, int n)
{
    int idx = blockIdx.x * blockDim.x + threadIdx.x;
    if (idx < n) b[idx] = a[idx];
}

// ---------------- host orchestration ----------------
extern "C" void kernel_launch(void* const* d_in, const int* in_sizes, int n_in,
                              void* d_out, int out_size)
{
    (void)in_sizes; (void)n_in;
    const float* img_emb   = (const float*)d_in[0];
    const float* queries   = (const float*)d_in[1];
    const float* vproj_w   = (const float*)d_in[2];
    const float* vproj_b   = (const float*)d_in[3];
    const float* lnv_g     = (const float*)d_in[4];
    const float* lnv_b     = (const float*)d_in[5];
    const float* m_in_w    = (const float*)d_in[6];
    const float* m_conv_w  = (const float*)d_in[7];
    const float* m_conv_b  = (const float*)d_in[8];
    const float* m_xproj_w = (const float*)d_in[9];
    const float* m_dt_w    = (const float*)d_in[10];
    const float* m_dt_b    = (const float*)d_in[11];
    const float* m_A_log   = (const float*)d_in[12];
    const float* m_D       = (const float*)d_in[13];
    const float* m_out_w   = (const float*)d_in[14];
    const float* sn_g      = (const float*)d_in[15];
    const float* sn_b      = (const float*)d_in[16];
    const float* at_in_w   = (const float*)d_in[17];
    const float* at_in_b   = (const float*)d_in[18];
    const float* at_out_w  = (const float*)d_in[19];
    const float* at_out_b  = (const float*)d_in[20];
    const float* cr_w      = (const float*)d_in[21];
    const float* cr_b      = (const float*)d_in[22];

    cudaFuncSetAttribute(gemm_bf16x2_kernel,
                         cudaFuncAttributeMaxDynamicSharedMemorySize, BF16_SMEM);

    float* AR = nullptr;
    cudaGetSymbolAddress((void**)&AR, g_arena);
    g_partial = AR + OFF_PART;

    float* feats = AR + OFF_FEATS;
    float* fwd   = AR + OFF_FWD;
    float* flip  = AR + OFF_FLIP;
    float* cbuf  = AR + OFF_C;
    float* mo    = AR + OFF_MO;
    float* xzb   = AR + OFF_XZ;
    float* xcb   = AR + OFF_XCB;
    float* dblb  = AR + OFF_DBL;
    float* dtb   = AR + OFF_DT;
    float* ysb   = AR + OFF_YS;
    float* xb    = AR + OFF_X;
    float* xnb   = AR + OFF_XN;
    float* qb    = AR + OFF_QB;
    float* ob    = AR + OFF_OB;
    float* catb  = AR + OFF_CAT;
    float* kvw   = AR + OFF_KVW;
    float* kvbias = AR + OFF_KVB;
    float* kvall = AR + OFF_KVALL;

    auto run_mamba = [&](const float* X, int ldx, int Lm, int i,
                         float* OUT, int ldout, const float* addend) {
        int Mrows = BATCH_ * Lm;
        gemm(X, ldx, m_in_w + (size_t)i * 2 * DI_ * DIMM, DIMM,
             nullptr, nullptr, 0, xzb, 2 * DI_, Mrows, 2 * DI_, DIMM, 0);
        conv_kernel<<<(BATCH_ * Lm * DI_ + 255) / 256, 256>>>(
            xzb, m_conv_w + (size_t)i * DI_ * DC_, m_conv_b + (size_t)i * DI_, xcb, Lm);
        gemm(xcb, DI_, m_xproj_w + (size_t)i * 80 * DI_, DI_,
             nullptr, nullptr, 0, dblb, 80, Mrows, 80, DI_, 0);
        gemm(dblb, 80, m_dt_w + (size_t)i * DI_ * DTR_, DTR_,
             m_dt_b + (size_t)i * DI_, nullptr, 0, dtb, DI_, Mrows, DI_, DTR_, 1);
        scan_kernel<<<(BATCH_ * DI_ * 4) / 256, 256>>>(
            dtb, dblb, xcb, xzb, m_A_log + (size_t)i * DI_ * DS_,
            m_D + (size_t)i * DI_, ysb, Lm);
        gemm(ysb, DI_, m_out_w + (size_t)i * DIMM * DI_, DI_,
             nullptr, addend, DIMM, OUT, ldout, Mrows, DIMM, DI_, 0);
    };

    // ---- Stage A ----
    gemm(img_emb, DIN_, vproj_w, DIN_, vproj_b, nullptr, 0,
         feats, DIMM, BATCH_ * LSEQ_, DIMM, DIN_, 0);
    ln_kernel<<<BATCH_ * LSEQ_, 256>>>(feats, lnv_g, lnv_b, feats);

    // ---- Stage B ----
    run_mamba(feats, DIMM, LSEQ_, 0, fwd, DIMM, nullptr);
    flip_kernel<<<(BATCH_ * LSEQ_ * DIMM + 255) / 256, 256>>>(feats, flip, LSEQ_);
    run_mamba(flip, DIMM, LSEQ_, 1, mo, DIMM, nullptr);
    add3_kernel<<<(BATCH_ * LSEQ_ * DIMM + 255) / 256, 256>>>(fwd, mo, feats, cbuf, LSEQ_);

    // ---- Batched KV for all 12 blocks ----
    kvgather_w<<<(NB_ * 2 * DIMM * DIMM + 255) / 256, 256>>>(at_in_w, kvw);
    kvgather_b<<<(NB_ * 2 * DIMM + 255) / 256, 256>>>(at_in_b, kvbias);
    gemm(cbuf, DIMM, kvw, DIMM, kvbias, nullptr, 0,
         kvall, NB_ * 2 * DIMM, BATCH_ * LSEQ_, NB_ * 2 * DIMM, DIMM, 0);

    // ---- Stage C ----
    bcast_kernel<<<(BATCH_ * NQ_ * DIMM + 255) / 256, 256>>>(queries, xb);

    for (int l = 0; l < NB_; l++) {
        ln_kernel<<<BATCH_ * NQ_, 256>>>(xb, sn_g + (size_t)l * DIMM, sn_b + (size_t)l * DIMM, xnb);
        run_mamba(xnb, DIMM, NQ_, l + 2, catb, 2 * DIMM, xnb);

        const float* wq = at_in_w + (size_t)l * 3 * DIMM * DIMM;
        const float* bq = at_in_b + (size_t)l * 3 * DIMM;
        gemm(catb, 2 * DIMM, wq, DIMM, bq, nullptr, 0, qb, DIMM, BATCH_ * NQ_, DIMM, DIMM, 0);

        attn_kernel<<<(BATCH_ * NQ_ * NH_ + 127) / 128, 128>>>(
            qb, kvall, ob, NB_ * 2 * DIMM, l * 2 * DIMM);

        gemm(ob, DIMM, at_out_w + (size_t)l * DIMM * DIMM, DIMM,
             at_out_b + (size_t)l * DIMM, nullptr, 0, catb + DIMM, 2 * DIMM,
             BATCH_ * NQ_, DIMM, DIMM, 0);

        gemm(catb, 2 * DIMM, cr_w + (size_t)l * DIMM * 2 * DIMM, 2 * DIMM,
             cr_b + (size_t)l * DIMM, nullptr, 0, xb, DIMM, BATCH_ * NQ_, DIMM, 2 * DIMM, 0);
    }

    copy_kernel<<<(out_size + 255) / 256, 256>>>(xb, (float*)d_out, out_size);
}

// round 7
// speedup vs baseline: 1.2031x; 1.2031x over previous
#include <cuda_runtime.h>
#include <cuda_bf16.h>
#include <math.h>
#include <stdint.h>

#define DIMM 768
#define DIN_ 1024
#define NQ_ 384
#define NB_ 12
#define BATCH_ 2
#define LSEQ_ 1024
#define DI_ 1536
#define DS_ 16
#define DC_ 4
#define DTR_ 48
#define NH_ 16
#define HD_ 48
#define NM_ 14

// ---------------- fp32 arena ----------------
#define SZ_BL_DIM   (BATCH_*LSEQ_*DIMM)
#define SZ_XZ       (BATCH_*LSEQ_*2*DI_)
#define SZ_XC       (BATCH_*LSEQ_*DI_)
#define SZ_DBL      (BATCH_*LSEQ_*80)
#define SZ_Q_DIM    (BATCH_*NQ_*DIMM)
#define SZ_CAT      (BATCH_*NQ_*2*DIMM)
#define SZ_KVB      (NB_*2*DIMM)
#define SZ_KVALL    (BATCH_*LSEQ_*NB_*2*DIMM)
#define SZ_PART     (8*1024*1024)

#define OFF_FEATS  ((size_t)0)
#define OFF_FWD    (OFF_FEATS + SZ_BL_DIM)
#define OFF_C      (OFF_FWD   + SZ_BL_DIM)
#define OFF_MO     (OFF_C     + SZ_BL_DIM)
#define OFF_XZ     (OFF_MO    + SZ_BL_DIM)
#define OFF_XCB    (OFF_XZ    + SZ_XZ)
#define OFF_DBL    (OFF_XCB   + SZ_XC)
#define OFF_DT     (OFF_DBL   + SZ_DBL)
#define OFF_X      (OFF_DT    + SZ_XC)
#define OFF_XN     (OFF_X     + SZ_Q_DIM)
#define OFF_QB     (OFF_XN    + SZ_Q_DIM)
#define OFF_CAT    (OFF_QB    + SZ_Q_DIM)
#define OFF_KVB    (OFF_CAT   + SZ_CAT)
#define OFF_KVALL  (OFF_KVB   + SZ_KVB)
#define OFF_PART   (OFF_KVALL + SZ_KVALL)
#define ARENA_SZ   (OFF_PART  + SZ_PART)

__device__ __align__(256) float g_arena[ARENA_SZ];

// ---------------- bf16 hi/lo plane arena ----------------
#define BSZ_IMG    (BATCH_*LSEQ_*DIN_)
#define BSZ_WVP    (DIMM*DIN_)
#define BSZ_WIN    (NM_*2*DI_*DIMM)
#define BSZ_WXP    (NM_*80*DI_)
#define BSZ_WDT    (NM_*DI_*DTR_)
#define BSZ_WOUT   (NM_*DIMM*DI_)
#define BSZ_WATIN  (NB_*3*DIMM*DIMM)
#define BSZ_WATOUT (NB_*DIMM*DIMM)
#define BSZ_WCR    (NB_*DIMM*2*DIMM)
#define BSZ_WKV    (NB_*2*DIMM*DIMM)

#define BO_IMG    ((size_t)0)
#define BO_FEATS  (BO_IMG    + 2*(size_t)BSZ_IMG)
#define BO_FLIP   (BO_FEATS  + 2*(size_t)SZ_BL_DIM)
#define BO_XN     (BO_FLIP   + 2*(size_t)SZ_BL_DIM)
#define BO_XC     (BO_XN     + 2*(size_t)SZ_Q_DIM)
#define BO_DBL    (BO_XC     + 2*(size_t)SZ_XC)
#define BO_YS     (BO_DBL    + 2*(size_t)SZ_DBL)
#define BO_CAT    (BO_YS     + 2*(size_t)SZ_XC)
#define BO_CBUF   (BO_CAT    + 2*(size_t)SZ_CAT)
#define BO_OB     (BO_CBUF   + 2*(size_t)SZ_BL_DIM)
#define BO_WVP    (BO_OB     + 2*(size_t)SZ_Q_DIM)
#define BO_WIN    (BO_WVP    + 2*(size_t)BSZ_WVP)
#define BO_WXP    (BO_WIN    + 2*(size_t)BSZ_WIN)
#define BO_WDT    (BO_WXP    + 2*(size_t)BSZ_WXP)
#define BO_WOUT   (BO_WDT    + 2*(size_t)BSZ_WDT)
#define BO_WATIN  (BO_WOUT   + 2*(size_t)BSZ_WOUT)
#define BO_WATOUT (BO_WATIN  + 2*(size_t)BSZ_WATIN)
#define BO_WCR    (BO_WATOUT + 2*(size_t)BSZ_WATOUT)
#define BO_WKV    (BO_WCR    + 2*(size_t)BSZ_WCR)
#define BAR_SZ    (BO_WKV    + 2*(size_t)BSZ_WKV)

__device__ __align__(256) __nv_bfloat16 g_bar[BAR_SZ];

// ---------------- helpers ----------------
__device__ __forceinline__ float softplusf(float x) {
    return fmaxf(x, 0.f) + log1pf(expf(-fabsf(x)));
}
__device__ __forceinline__ float siluf(float x) {
    return x / (1.f + expf(-x));
}
__device__ __forceinline__ void emit_hl(float v, __nv_bfloat16* p, size_t plane, size_t off) {
    __nv_bfloat16 hb = __float2bfloat16_rn(v);
    p[off] = hb;
    p[plane + off] = __float2bfloat16_rn(v - __bfloat162float(hb));
}

#define MMA_BF16(d, a, b0, b1) \
    asm volatile("mma.sync.aligned.m16n8k16.row.col.f32.bf16.bf16.f32 " \
        "{%0,%1,%2,%3}, {%4,%5,%6,%7}, {%8,%9}, {%0,%1,%2,%3};" \
        : "+f"(d[0]), "+f"(d[1]), "+f"(d[2]), "+f"(d[3]) \
        : "r"(a[0]), "r"(a[1]), "r"(a[2]), "r"(a[3]), "r"(b0), "r"(b1))

#define LDSM4(r, addr) \
    asm volatile("ldmatrix.sync.aligned.m8n8.x4.shared.b16 {%0,%1,%2,%3}, [%4];" \
        : "=r"((r)[0]), "=r"((r)[1]), "=r"((r)[2]), "=r"((r)[3]) : "r"(addr))

// ================= bf16 hi/lo tensor-core GEMM, cp.async 3-stage =================
// 128x128 tile, BK=32, 256 thr, warps 4(M)x2(N). Tiles per stage: AH|AL|BH|BL,
// each 128 rows x 64B, XOR-swizzled (col16 ^= (row>>1)&3). stage = 32 KB.
#define STAGE_BYTES 32768
#define GEMM_SMEM (3 * STAGE_BYTES)

__global__ __launch_bounds__(256, 2) void gemm_bf_kernel(
    const __nv_bfloat16* __restrict__ Ah, size_t Apl, int lda,
    const __nv_bfloat16* __restrict__ Bh, size_t Bpl, int ldb,
    const float* __restrict__ bias,
    const float* __restrict__ addend, int ldadd,
    float* __restrict__ C, __nv_bfloat16* __restrict__ Cb, size_t Cpl,
    int ldc, size_t zstride,
    int M, int N, int klen, int act)
{
    extern __shared__ uint8_t smem_raw[];
    uint32_t sbase = (uint32_t)__cvta_generic_to_shared(smem_raw);
    int tid = threadIdx.x;
    int bm = blockIdx.y * 128, bn = blockIdx.x * 128;
    int kbeg = blockIdx.z * klen, kend = kbeg + klen;

    auto load_stage = [&](int sidx, int kbase, bool doload) {
        if (doload) {
            uint32_t sb = sbase + (uint32_t)sidx * STAGE_BYTES;
#pragma unroll
            for (int i = 0; i < 8; i++) {
                int cid = i * 256 + tid;
                int tile = cid >> 9;
                int within = cid & 511;
                int row = within >> 2;
                int c = within & 3;
                int swc = c ^ ((row >> 1) & 3);
                uint32_t dst = sb + tile * 8192 + row * 64 + swc * 16;
                int k = kbase + c * 8;
                const __nv_bfloat16* src;
                bool rv;
                if (tile < 2) {
                    int gr = bm + row;
                    rv = gr < M;
                    src = Ah + (tile ? Apl : 0) + (size_t)(rv ? gr : 0) * lda + k;
                } else {
                    int gr = bn + row;
                    rv = gr < N;
                    src = Bh + (tile == 3 ? Bpl : 0) + (size_t)(rv ? gr : 0) * ldb + k;
                }
                int sz = (rv && k < kend) ? 16 : 0;
                asm volatile("cp.async.cg.shared.global [%0], [%1], 16, %2;\n"
                             :: "r"(dst), "l"(src), "r"(sz));
            }
        }
        asm volatile("cp.async.commit_group;\n");
    };

    int lane = tid & 31, warp = tid >> 5;
    int wm = warp & 3, wn = warp >> 2;
    int m0 = wm * 32, n0 = wn * 64;
    int lr = lane >> 2, lc = lane & 3;
    int j8 = lane >> 3, rj = lane & 7;

    int a_rl = ((j8 & 1) << 3) + rj;   // row within 16-row A tile
    int a_kq = j8 >> 1;                 // 16B col within k16
    int b_rl = ((j8 >> 1) << 3) + rj;
    int b_kq = j8 & 1;

    uint32_t a_off[2], a_msk[2];
#pragma unroll
    for (int mi = 0; mi < 2; mi++) {
        int row = m0 + mi * 16 + a_rl;
        a_off[mi] = row * 64;
        a_msk[mi] = (row >> 1) & 3;
    }
    uint32_t b_off[4], b_msk[4];
#pragma unroll
    for (int pr = 0; pr < 4; pr++) {
        int row = n0 + pr * 16 + b_rl;
        b_off[pr] = row * 64;
        b_msk[pr] = (row >> 1) & 3;
    }

    float acc[2][8][4];
#pragma unroll
    for (int mi = 0; mi < 2; mi++)
#pragma unroll
        for (int ni = 0; ni < 8; ni++)
#pragma unroll
            for (int r = 0; r < 4; r++) acc[mi][ni][r] = 0.f;

    int nsteps = (klen + 31) / 32;
    load_stage(0, kbeg, true);
    load_stage(1, kbeg + 32, nsteps > 1);

    int buf = 0;
    for (int s = 0; s < nsteps; s++) {
        asm volatile("cp.async.wait_group 1;\n");
        __syncthreads();
        int s2 = s + 2;
        load_stage(s2 % 3, kbeg + s2 * 32, s2 < nsteps);

        uint32_t sb = sbase + (uint32_t)buf * STAGE_BYTES;
#pragma unroll
        for (int c = 0; c < 2; c++) {
            uint32_t afh[2][4], afl[2][4];
#pragma unroll
            for (int mi = 0; mi < 2; mi++) {
                uint32_t col = ((uint32_t)(a_kq + c * 2)) ^ a_msk[mi];
                uint32_t ad = sb + a_off[mi] + col * 16;
                LDSM4(afh[mi], ad);
                LDSM4(afl[mi], ad + 8192);
            }
#pragma unroll
            for (int pr = 0; pr < 4; pr++) {
                uint32_t col = ((uint32_t)(b_kq + c * 2)) ^ b_msk[pr];
                uint32_t bd = sb + 16384 + b_off[pr] + col * 16;
                uint32_t bhm[4], blm[4];
                LDSM4(bhm, bd);
                LDSM4(blm, bd + 8192);
#pragma unroll
                for (int mi = 0; mi < 2; mi++) {
                    MMA_BF16(acc[mi][2*pr],   afh[mi], bhm[0], bhm[1]);
                    MMA_BF16(acc[mi][2*pr],   afh[mi], blm[0], blm[1]);
                    MMA_BF16(acc[mi][2*pr],   afl[mi], bhm[0], bhm[1]);
                    MMA_BF16(acc[mi][2*pr+1], afh[mi], bhm[2], bhm[3]);
                    MMA_BF16(acc[mi][2*pr+1], afh[mi], blm[2], blm[3]);
                    MMA_BF16(acc[mi][2*pr+1], afl[mi], bhm[2], bhm[3]);
                }
            }
        }
        buf = (buf + 1) % 3;
    }

    float* Cz = C + (size_t)blockIdx.z * zstride;
#pragma unroll
    for (int mi = 0; mi < 2; mi++) {
#pragma unroll
        for (int rh = 0; rh < 2; rh++) {
            int m = bm + m0 + mi * 16 + lr + rh * 8;
            if (m >= M) continue;
#pragma unroll
            for (int ni = 0; ni < 8; ni++) {
#pragma unroll
                for (int cc = 0; cc < 2; cc++) {
                    int n = bn + n0 + ni * 8 + 2 * lc + cc;
                    if (n >= N) continue;
                    float v = acc[mi][ni][rh * 2 + cc];
                    if (bias) v += bias[n];
                    if (act == 1) v = softplusf(v);
                    if (addend) v += addend[(size_t)m * ldadd + n];
                    size_t co = (size_t)m * ldc + n;
                    Cz[co] = v;
                    if (Cb) emit_hl(v, Cb, Cpl, co);
                }
            }
        }
    }
}

// ============ split-K reduce with epilogue ============
__global__ void reduce_kernel(const float* __restrict__ part, size_t pstride, int nsplit,
                              const float* __restrict__ bias,
                              const float* __restrict__ addend, int ldadd,
                              float* __restrict__ C, __nv_bfloat16* __restrict__ Cb,
                              size_t Cpl, int ldc, int M, int N, int act)
{
    int idx = blockIdx.x * blockDim.x + threadIdx.x;
    if (idx >= M * N) return;
    int m = idx / N, n = idx % N;
    float v = 0.f;
    for (int z = 0; z < nsplit; z++) v += part[(size_t)z * pstride + idx];
    if (bias) v += bias[n];
    if (act == 1) v = softplusf(v);
    if (addend) v += addend[(size_t)m * ldadd + n];
    size_t co = (size_t)m * ldc + n;
    C[co] = v;
    if (Cb) emit_hl(v, Cb, Cpl, co);
}

static float* g_partial = nullptr;

static void gemm(const __nv_bfloat16* Ah, size_t Apl, int lda,
                 const __nv_bfloat16* Bh, size_t Bpl, int ldb,
                 const float* bias, const float* addend, int ldadd,
                 float* C, __nv_bfloat16* Cb, size_t Cpl, int ldc,
                 int M, int N, int K, int act)
{
    int gm = (M + 127) / 128, gn = (N + 127) / 128;
    int split = 1;
    while (gm * gn * split < 132 && split < 8 &&
           (K % (split * 2)) == 0 && (K / (split * 2)) >= 48 &&
           ((K / (split * 2)) % 16) == 0) split *= 2;
    int klen = K / split;
    dim3 grid(gn, gm, split);
    if (split == 1) {
        gemm_bf_kernel<<<grid, 256, GEMM_SMEM>>>(
            Ah, Apl, lda, Bh, Bpl, ldb, bias, addend, ldadd,
            C, Cb, Cpl, ldc, 0, M, N, klen, act);
    } else {
        gemm_bf_kernel<<<grid, 256, GEMM_SMEM>>>(
            Ah, Apl, lda, Bh, Bpl, ldb, nullptr, nullptr, 0,
            g_partial, nullptr, 0, N, (size_t)M * N, M, N, klen, 0);
        reduce_kernel<<<(M * N + 255) / 256, 256>>>(
            g_partial, (size_t)M * N, split, bias, addend, ldadd,
            C, Cb, Cpl, ldc, M, N, act);
    }
}

// ---------------- fp32 -> bf16 hi/lo conversion ----------------
__global__ void cvt_kernel(const float* __restrict__ x, __nv_bfloat16* __restrict__ d,
                           size_t plane, int n)
{
    int i = blockIdx.x * blockDim.x + threadIdx.x;
    if (i >= n) return;
    emit_hl(x[i], d, plane, (size_t)i);
}

// ---------------- layernorm (+bf16 emit) ----------------
__global__ void ln_kernel(const float* __restrict__ x, const float* __restrict__ g,
                          const float* __restrict__ b, float* __restrict__ y,
                          __nv_bfloat16* __restrict__ yb, size_t plane)
{
    int r = blockIdx.x;
    const float* xp = x + (size_t)r * DIMM;
    float s = 0.f, ss = 0.f;
    for (int i = threadIdx.x; i < DIMM; i += blockDim.x) {
        float v = xp[i]; s += v; ss += v * v;
    }
    __shared__ float shs[8], shss[8];
    for (int o = 16; o > 0; o >>= 1) {
        s += __shfl_xor_sync(0xffffffffu, s, o);
        ss += __shfl_xor_sync(0xffffffffu, ss, o);
    }
    int w = threadIdx.x >> 5;
    if ((threadIdx.x & 31) == 0) { shs[w] = s; shss[w] = ss; }
    __syncthreads();
    if (threadIdx.x == 0) {
        float ts = 0.f, tss = 0.f;
        int nw = blockDim.x >> 5;
        for (int i = 0; i < nw; i++) { ts += shs[i]; tss += shss[i]; }
        shs[0] = ts; shss[0] = tss;
    }
    __syncthreads();
    float mean = shs[0] / (float)DIMM;
    float var = shss[0] / (float)DIMM - mean * mean;
    float inv = rsqrtf(var + 1e-5f);
    float* yp = y + (size_t)r * DIMM;
    for (int i = threadIdx.x; i < DIMM; i += blockDim.x) {
        float v = (xp[i] - mean) * inv * g[i] + b[i];
        yp[i] = v;
        if (yb) emit_hl(v, yb, plane, (size_t)r * DIMM + i);
    }
}

// ---------------- depthwise causal conv + silu (+bf16 emit) ----------------
__global__ void conv_kernel(const float* __restrict__ xz, const float* __restrict__ cw,
                            const float* __restrict__ cb, float* __restrict__ xc,
                            __nv_bfloat16* __restrict__ xcb16, size_t plane, int L)
{
    int idx = blockIdx.x * blockDim.x + threadIdx.x;
    int total = BATCH_ * L * DI_;
    if (idx >= total) return;
    int d = idx % DI_;
    int l = (idx / DI_) % L;
    int b = idx / (DI_ * L);
    float sum = cb[d];
    const float* base = xz + ((size_t)b * L) * (2 * DI_) + d;
#pragma unroll
    for (int j = 0; j < DC_; j++) {
        int lt = l - (DC_ - 1) + j;
        if (lt >= 0) sum += base[(size_t)lt * (2 * DI_)] * cw[d * DC_ + j];
    }
    float v = siluf(sum);
    xc[idx] = v;
    emit_hl(v, xcb16, plane, (size_t)idx);
}

// ---------------- selective scan: 4 states/thread (bf16 emit out) ----------------
__global__ void scan_kernel(const float* __restrict__ dt, const float* __restrict__ dbl,
                            const float* __restrict__ xc, const float* __restrict__ xz,
                            const float* __restrict__ A_log, const float* __restrict__ Dp,
                            __nv_bfloat16* __restrict__ ysb16, size_t plane, int L)
{
    int idx = blockIdx.x * blockDim.x + threadIdx.x;
    int sq = idx & 3;
    int s4 = sq * 4;
    int bd = idx >> 2;
    int d = bd % DI_;
    int b = bd / DI_;

    float Av[4];
#pragma unroll
    for (int q = 0; q < 4; q++) Av[q] = -__expf(A_log[d * DS_ + s4 + q]);
    float Dv = Dp[d];
    float h[4] = {0.f, 0.f, 0.f, 0.f};

    const float* dt_p = dt + (size_t)b * L * DI_ + d;
    const float* xc_p = xc + (size_t)b * L * DI_ + d;
    const float* z_p = xz + (size_t)b * L * (2 * DI_) + DI_ + d;
    const float* bl_p = dbl + (size_t)b * L * 80;
    size_t ys_o = (size_t)b * L * DI_ + d;

    float dtv = dt_p[0];
    float xcv = xc_p[0];
    float4 Bv = *(const float4*)(bl_p + 48 + s4);
    float4 Cv = *(const float4*)(bl_p + 64 + s4);
    float zv = (sq == 0) ? z_p[0] : 0.f;

    for (int t = 0; t < L; t++) {
        float dtn = 0.f, xcn = 0.f, zn = 0.f;
        float4 Bn = make_float4(0.f, 0.f, 0.f, 0.f);
        float4 Cn = Bn;
        if (t + 1 < L) {
            size_t t1 = t + 1;
            dtn = dt_p[t1 * DI_];
            xcn = xc_p[t1 * DI_];
            Bn = *(const float4*)(bl_p + t1 * 80 + 48 + s4);
            Cn = *(const float4*)(bl_p + t1 * 80 + 64 + s4);
            if (sq == 0) zn = z_p[t1 * (2 * DI_)];
        }
        float dx = dtv * xcv;
        float Bb[4] = {Bv.x, Bv.y, Bv.z, Bv.w};
        float Cc[4] = {Cv.x, Cv.y, Cv.z, Cv.w};
        float pr = 0.f;
#pragma unroll
        for (int q = 0; q < 4; q++) {
            h[q] = __expf(dtv * Av[q]) * h[q] + dx * Bb[q];
            pr += h[q] * Cc[q];
        }
        pr += __shfl_xor_sync(0xffffffffu, pr, 2);
        pr += __shfl_xor_sync(0xffffffffu, pr, 1);
        if (sq == 0) {
            float y = (pr + Dv * xcv) * siluf(zv);
            emit_hl(y, ysb16, plane, ys_o + (size_t)t * DI_);
        }
        dtv = dtn; xcv = xcn; Bv = Bn; Cv = Cn; zv = zn;
    }
}

// ---------------- local cross-attention (bf16 emit out) ----------------
__global__ void attn_kernel(const float* __restrict__ q, const float* __restrict__ kv,
                            __nv_bfloat16* __restrict__ o16, size_t plane,
                            int ldkv, int loff)
{
    int idx = blockIdx.x * blockDim.x + threadIdx.x;
    if (idx >= BATCH_ * NQ_ * NH_) return;
    int h = idx % NH_;
    int qi = (idx / NH_) % NQ_;
    int b = idx / (NH_ * NQ_);
    const int kpq = LSEQ_ / NQ_;
    const int extra = LSEQ_ % NQ_;
    int start = qi * kpq + (qi < extra ? qi : extra);
    int cnt = kpq + (qi < extra ? 1 : 0);
    const float* qp = q + ((size_t)(b * NQ_ + qi)) * DIMM + h * HD_;
    float s[3];
    float mx = -1e30f;
    for (int j = 0; j < cnt; j++) {
        const float* kp = kv + ((size_t)(b * LSEQ_ + start + j)) * ldkv + loff + h * HD_;
        float dot = 0.f;
#pragma unroll
        for (int d = 0; d < HD_; d++) dot += qp[d] * kp[d];
        dot *= 0.14433756729740643f;
        s[j] = dot;
        if (dot > mx) mx = dot;
    }
    float sum = 0.f;
    for (int j = 0; j < cnt; j++) { s[j] = expf(s[j] - mx); sum += s[j]; }
    float inv = 1.f / sum;
    size_t oo = ((size_t)(b * NQ_ + qi)) * DIMM + h * HD_;
    for (int d = 0; d < HD_; d++) {
        float acc = 0.f;
        for (int j = 0; j < cnt; j++)
            acc += s[j] * kv[((size_t)(b * LSEQ_ + start + j)) * ldkv + loff + DIMM + h * HD_ + d];
        emit_hl(acc * inv, o16, plane, oo + d);
    }
}

// ---------------- kv weight gather (fp32 -> bf16 planes) + bias ----------------
__global__ void kvgather_w(const float* __restrict__ w, __nv_bfloat16* __restrict__ out,
                           size_t plane)
{
    int idx = blockIdx.x * blockDim.x + threadIdx.x;
    int total = NB_ * 2 * DIMM * DIMM;
    if (idx >= total) return;
    int n = idx / DIMM, k = idx % DIMM;
    int l = n / (2 * DIMM), r = n % (2 * DIMM);
    emit_hl(w[((size_t)l * 3 * DIMM + DIMM + r) * DIMM + k], out, plane, (size_t)idx);
}
__global__ void kvgather_b(const float* __restrict__ b, float* __restrict__ out)
{
    int n = blockIdx.x * blockDim.x + threadIdx.x;
    if (n >= NB_ * 2 * DIMM) return;
    int l = n / (2 * DIMM), r = n % (2 * DIMM);
    out[n] = b[(size_t)l * 3 * DIMM + DIMM + r];
}

// ---------------- elementwise utilities ----------------
__global__ void flip_kernel(const float* __restrict__ in, __nv_bfloat16* __restrict__ out,
                            size_t plane, int L)
{
    int idx = blockIdx.x * blockDim.x + threadIdx.x;
    int total = BATCH_ * L * DIMM;
    if (idx >= total) return;
    int d = idx % DIMM;
    int l = (idx / DIMM) % L;
    int b = idx / (DIMM * L);
    emit_hl(in[((size_t)b * L + (L - 1 - l)) * DIMM + d], out, plane, (size_t)idx);
}

__global__ void add3_kernel(const float* __restrict__ fwd, const float* __restrict__ mo,
                            const float* __restrict__ feats,
                            __nv_bfloat16* __restrict__ c16, size_t plane, int L)
{
    int idx = blockIdx.x * blockDim.x + threadIdx.x;
    int total = BATCH_ * L * DIMM;
    if (idx >= total) return;
    int d = idx % DIMM;
    int l = (idx / DIMM) % L;
    int b = idx / (DIMM * L);
    float v = fwd[idx] + mo[((size_t)b * L + (L - 1 - l)) * DIMM + d] + feats[idx];
    emit_hl(v, c16, plane, (size_t)idx);
}

__global__ void bcast_kernel(const float* __restrict__ queries, float* __restrict__ x)
{
    int idx = blockIdx.x * blockDim.x + threadIdx.x;
    int total = BATCH_ * NQ_ * DIMM;
    if (idx >= total) return;
    x[idx] = queries[idx % (NQ_ * DIMM)];
}

__global__ void copy_kernel(const float* __restrict__ a, float* __restrict__ b, int n)
{
    int idx = blockIdx.x * blockDim.x + threadIdx.x;
    if (idx < n) b[idx] = a[idx];
}

// ---------------- host orchestration ----------------
extern "C" void kernel_launch(void* const* d_in, const int* in_sizes, int n_in,
                              void* d_out, int out_size)
{
    (void)in_sizes; (void)n_in;
    const float* img_emb   = (const float*)d_in[0];
    const float* queries   = (const float*)d_in[1];
    const float* vproj_w   = (const float*)d_in[2];
    const float* vproj_b   = (const float*)d_in[3];
    const float* lnv_g     = (const float*)d_in[4];
    const float* lnv_b     = (const float*)d_in[5];
    const float* m_in_w    = (const float*)d_in[6];
    const float* m_conv_w  = (const float*)d_in[7];
    const float* m_conv_b  = (const float*)d_in[8];
    const float* m_xproj_w = (const float*)d_in[9];
    const float* m_dt_w    = (const float*)d_in[10];
    const float* m_dt_b    = (const float*)d_in[11];
    const float* m_A_log   = (const float*)d_in[12];
    const float* m_D       = (const float*)d_in[13];
    const float* m_out_w   = (const float*)d_in[14];
    const float* sn_g      = (const float*)d_in[15];
    const float* sn_b      = (const float*)d_in[16];
    const float* at_in_w   = (const float*)d_in[17];
    const float* at_in_b   = (const float*)d_in[18];
    const float* at_out_w  = (const float*)d_in[19];
    const float* at_out_b  = (const float*)d_in[20];
    const float* cr_w      = (const float*)d_in[21];
    const float* cr_b      = (const float*)d_in[22];

    cudaFuncSetAttribute(gemm_bf_kernel,
                         cudaFuncAttributeMaxDynamicSharedMemorySize, GEMM_SMEM);

    float* AR = nullptr;
    cudaGetSymbolAddress((void**)&AR, g_arena);
    __nv_bfloat16* BR = nullptr;
    cudaGetSymbolAddress((void**)&BR, g_bar);
    g_partial = AR + OFF_PART;

    float* feats = AR + OFF_FEATS;
    float* fwd   = AR + OFF_FWD;
    float* mo    = AR + OFF_MO;
    float* xzb   = AR + OFF_XZ;
    float* xcb   = AR + OFF_XCB;
    float* dblb  = AR + OFF_DBL;
    float* dtb   = AR + OFF_DT;
    float* xb    = AR + OFF_X;
    float* xnb   = AR + OFF_XN;
    float* qb    = AR + OFF_QB;
    float* catb  = AR + OFF_CAT;
    float* kvbias = AR + OFF_KVB;
    float* kvall = AR + OFF_KVALL;

    __nv_bfloat16* bImg   = BR + BO_IMG;
    __nv_bfloat16* bFeats = BR + BO_FEATS;
    __nv_bfloat16* bFlip  = BR + BO_FLIP;
    __nv_bfloat16* bXn    = BR + BO_XN;
    __nv_bfloat16* bXc    = BR + BO_XC;
    __nv_bfloat16* bDbl   = BR + BO_DBL;
    __nv_bfloat16* bYs    = BR + BO_YS;
    __nv_bfloat16* bCat   = BR + BO_CAT;
    __nv_bfloat16* bCbuf  = BR + BO_CBUF;
    __nv_bfloat16* bOb    = BR + BO_OB;
    __nv_bfloat16* wVp    = BR + BO_WVP;
    __nv_bfloat16* wIn    = BR + BO_WIN;
    __nv_bfloat16* wXp    = BR + BO_WXP;
    __nv_bfloat16* wDt    = BR + BO_WDT;
    __nv_bfloat16* wOut   = BR + BO_WOUT;
    __nv_bfloat16* wAtin  = BR + BO_WATIN;
    __nv_bfloat16* wAtout = BR + BO_WATOUT;
    __nv_bfloat16* wCr    = BR + BO_WCR;
    __nv_bfloat16* wKv    = BR + BO_WKV;

    auto cvt = [&](const float* s, __nv_bfloat16* d, size_t plane, int n) {
        cvt_kernel<<<(n + 255) / 256, 256>>>(s, d, plane, n);
    };

    // ---- weight + input conversions ----
    cvt(img_emb, bImg, BSZ_IMG, BSZ_IMG);
    cvt(vproj_w, wVp, BSZ_WVP, BSZ_WVP);
    cvt(m_in_w, wIn, BSZ_WIN, BSZ_WIN);
    cvt(m_xproj_w, wXp, BSZ_WXP, BSZ_WXP);
    cvt(m_dt_w, wDt, BSZ_WDT, BSZ_WDT);
    cvt(m_out_w, wOut, BSZ_WOUT, BSZ_WOUT);
    cvt(at_in_w, wAtin, BSZ_WATIN, BSZ_WATIN);
    cvt(at_out_w, wAtout, BSZ_WATOUT, BSZ_WATOUT);
    cvt(cr_w, wCr, BSZ_WCR, BSZ_WCR);
    kvgather_w<<<(NB_ * 2 * DIMM * DIMM + 255) / 256, 256>>>(at_in_w, wKv, BSZ_WKV);
    kvgather_b<<<(NB_ * 2 * DIMM + 255) / 256, 256>>>(at_in_b, kvbias);

    // run_mamba: A-operand = bX (bf16 planes of input, ld ldx)
    auto run_mamba = [&](const __nv_bfloat16* bX, size_t xpl, int ldx, int Lm, int i,
                         float* OUT, __nv_bfloat16* OUTb, size_t outpl, int ldout,
                         const float* addend) {
        int Mrows = BATCH_ * Lm;
        gemm(bX, xpl, ldx, wIn + (size_t)i * 2 * DI_ * DIMM, BSZ_WIN, DIMM,
             nullptr, nullptr, 0, xzb, nullptr, 0, 2 * DI_, Mrows, 2 * DI_, DIMM, 0);
        conv_kernel<<<(BATCH_ * Lm * DI_ + 255) / 256, 256>>>(
            xzb, m_conv_w + (size_t)i * DI_ * DC_, m_conv_b + (size_t)i * DI_,
            xcb, bXc, SZ_XC, Lm);
        gemm(bXc, SZ_XC, DI_, wXp + (size_t)i * 80 * DI_, BSZ_WXP, DI_,
             nullptr, nullptr, 0, dblb, bDbl, SZ_DBL, 80, Mrows, 80, DI_, 0);
        gemm(bDbl, SZ_DBL, 80, wDt + (size_t)i * DI_ * DTR_, BSZ_WDT, DTR_,
             m_dt_b + (size_t)i * DI_, nullptr, 0, dtb, nullptr, 0, DI_,
             Mrows, DI_, DTR_, 1);
        scan_kernel<<<(BATCH_ * DI_ * 4) / 256, 256>>>(
            dtb, dblb, xcb, xzb, m_A_log + (size_t)i * DI_ * DS_,
            m_D + (size_t)i * DI_, bYs, SZ_XC, Lm);
        gemm(bYs, SZ_XC, DI_, wOut + (size_t)i * DIMM * DI_, BSZ_WOUT, DI_,
             nullptr, addend, DIMM, OUT, OUTb, outpl, ldout, Mrows, DIMM, DI_, 0);
    };

    // ---- Stage A ----
    gemm(bImg, BSZ_IMG, DIN_, wVp, BSZ_WVP, DIN_, vproj_b, nullptr, 0,
         feats, nullptr, 0, DIMM, BATCH_ * LSEQ_, DIMM, DIN_, 0);
    ln_kernel<<<BATCH_ * LSEQ_, 256>>>(feats, lnv_g, lnv_b, feats, bFeats, SZ_BL_DIM);

    // ---- Stage B ----
    run_mamba(bFeats, SZ_BL_DIM, DIMM, LSEQ_, 0, fwd, nullptr, 0, DIMM, nullptr);
    flip_kernel<<<(BATCH_ * LSEQ_ * DIMM + 255) / 256, 256>>>(feats, bFlip, SZ_BL_DIM, LSEQ_);
    run_mamba(bFlip, SZ_BL_DIM, DIMM, LSEQ_, 1, mo, nullptr, 0, DIMM, nullptr);
    add3_kernel<<<(BATCH_ * LSEQ_ * DIMM + 255) / 256, 256>>>(fwd, mo, feats, bCbuf, SZ_BL_DIM, LSEQ_);

    // ---- Batched KV for all 12 blocks ----
    gemm(bCbuf, SZ_BL_DIM, DIMM, wKv, BSZ_WKV, DIMM, kvbias, nullptr, 0,
         kvall, nullptr, 0, NB_ * 2 * DIMM, BATCH_ * LSEQ_, NB_ * 2 * DIMM, DIMM, 0);

    // ---- Stage C ----
    bcast_kernel<<<(BATCH_ * NQ_ * DIMM + 255) / 256, 256>>>(queries, xb);

    for (int l = 0; l < NB_; l++) {
        ln_kernel<<<BATCH_ * NQ_, 256>>>(xb, sn_g + (size_t)l * DIMM,
                                         sn_b + (size_t)l * DIMM, xnb, bXn, SZ_Q_DIM);
        // x_mid = mamba(xn)+xn -> catb/bCat cols [0,768), ld 1536
        run_mamba(bXn, SZ_Q_DIM, DIMM, NQ_, l + 2, catb, bCat, SZ_CAT, 2 * DIMM, xnb);

        const __nv_bfloat16* wq = wAtin + (size_t)l * 3 * DIMM * DIMM;
        const float* bq = at_in_b + (size_t)l * 3 * DIMM;
        gemm(bCat, SZ_CAT, 2 * DIMM, wq, BSZ_WATIN, DIMM, bq, nullptr, 0,
             qb, nullptr, 0, DIMM, BATCH_ * NQ_, DIMM, DIMM, 0);

        attn_kernel<<<(BATCH_ * NQ_ * NH_ + 127) / 128, 128>>>(
            qb, kvall, bOb, SZ_Q_DIM, NB_ * 2 * DIMM, l * 2 * DIMM);

        // score -> catb/bCat cols [768,1536)
        gemm(bOb, SZ_Q_DIM, DIMM, wAtout + (size_t)l * DIMM * DIMM, BSZ_WATOUT, DIMM,
             at_out_b + (size_t)l * DIMM, nullptr, 0, catb + DIMM, bCat + DIMM, SZ_CAT,
             2 * DIMM, BATCH_ * NQ_, DIMM, DIMM, 0);

        // x = [x_mid, score] @ cross_w.T + cross_b
        gemm(bCat, SZ_CAT, 2 * DIMM, wCr + (size_t)l * DIMM * 2 * DIMM, BSZ_WCR, 2 * DIMM,
             cr_b + (size_t)l * DIMM, nullptr, 0, xb, nullptr, 0, DIMM,
             BATCH_ * NQ_, DIMM, 2 * DIMM, 0);
    }

    copy_kernel<<<(out_size + 255) / 256, 256>>>(xb, (float*)d_out, out_size);
}